// round 17
// baseline (speedup 1.0000x reference)
#include <cuda_runtime.h>
#include <cuda_fp16.h>
#include <cstdint>

// Problem dims
#define B_SZ 8
#define CIN 576
#define C_OUT 192
#define KK 9
#define H_IMG 56
#define W_IMG 56
#define HW 3136
#define M_G 1728
#define N_G 3136
#define K_G 576
#define KP 576               // K' = 576: plain fp16 single-term GEMM

// Scratch (device globals: referenced ONLY from device code!)
__device__ float g_logits[(size_t)B_SZ * M_G * N_G];                  // 173 MB
__device__ __half g_At[(size_t)M_G * KP];                             // 2 MB
__device__ __half g_Xt[(size_t)B_SZ * N_G * KP];                      // 29 MB

__device__ __forceinline__ uint32_t smem_u32(const void* p) {
    uint32_t a;
    asm("{ .reg .u64 t; cvta.to.shared.u64 t, %1; cvt.u32.u64 %0, t; }"
        : "=r"(a) : "l"(p));
    return a;
}

// ---------------------------------------------------------------------------
// Pack A: fc_w (1728x576) fp32 -> At (1728x576) fp16
// ---------------------------------------------------------------------------
__global__ void pack_A_kernel(const float* __restrict__ fc_w) {
    const int e = blockIdx.x * 256 + threadIdx.x;
    if (e >= M_G * K_G) return;
    g_At[e] = __float2half(fc_w[e]);
}

// ---------------------------------------------------------------------------
// Pack X: x (8,576,3136) fp32 -> Xt (8,3136,576) fp16 (transposed), half2 st.
// ---------------------------------------------------------------------------
__global__ __launch_bounds__(256)
void pack_X_kernel(const float* __restrict__ x) {
    __shared__ float t[32][33];
    const int bz = blockIdx.z;
    const int k0 = blockIdx.y * 32;
    const int n0 = blockIdx.x * 32;
    const int tx = threadIdx.x & 31;
    const int ty = threadIdx.x >> 5;   // 0..7

    const float* xb = x + (size_t)bz * CIN * HW;
#pragma unroll
    for (int i = 0; i < 4; i++) {
        const int k = k0 + ty + i * 8;
        t[ty + i * 8][tx] = xb[(size_t)k * HW + n0 + tx];
    }
    __syncthreads();

    __half* Xb = g_Xt + (size_t)bz * N_G * KP;
    const int kp2 = threadIdx.x & 15;
    const int nl  = threadIdx.x >> 4;
#pragma unroll
    for (int i = 0; i < 2; i++) {
        const int n_local = nl + i * 16;
        const int n = n0 + n_local;
        __half2 hh;
        hh.x = __float2half(t[2 * kp2][n_local]);
        hh.y = __float2half(t[2 * kp2 + 1][n_local]);
        *reinterpret_cast<__half2*>(Xb + (size_t)n * KP + k0 + 2 * kp2) = hh;
    }
}

// ---------------------------------------------------------------------------
// HMMA GEMM (fp16 in, fp32 accum), cp.async 3-buffer ring — R16-verified.
// ---------------------------------------------------------------------------
#define KS 64
#define NST 9                          // 576/64
#define RSTRIDE 72
#define TILE_ELEMS (128 * RSTRIDE)
#define TILE_BYTES (TILE_ELEMS * 2)
#define PAIR_BYTES (2 * TILE_BYTES)
#define DSMEM_BYTES (3 * PAIR_BYTES)   // 110592

__global__ __launch_bounds__(256, 2)
void gemm_mma_kernel()
{
    extern __shared__ __align__(16) __half smp[];

    const int tid  = threadIdx.x;
    const int lane = tid & 31;
    const int wid  = tid >> 5;
    const int wm   = wid >> 1;
    const int wn   = wid & 1;

    const int b  = blockIdx.z;
    const int m0 = blockIdx.y * 128;
    const int n0 = blockIdx.x * 128;
    const __half* At = g_At;
    const __half* Xb = g_Xt + (size_t)b * N_G * KP;
    float* Cp = g_logits + (size_t)b * M_G * N_G;

    const uint32_t smA0 = smem_u32(smp);
    const uint32_t smB0 = smA0 + TILE_BYTES;

    float acc[2][8][4];
#pragma unroll
    for (int mt = 0; mt < 2; mt++)
#pragma unroll
        for (int nt = 0; nt < 8; nt++)
#pragma unroll
            for (int r = 0; r < 4; r++) acc[mt][nt][r] = 0.f;

    int rowc[4], kcc[4];
#pragma unroll
    for (int i = 0; i < 4; i++) {
        const int ch = tid + i * 256;
        rowc[i] = ch >> 3;
        kcc[i]  = ch & 7;
    }

    const int m_off  = (lane & 7) + ((lane >> 3) & 1) * 8;
    const int ka_off = (lane >> 4) * 8;
    const int n_off  = (lane & 7) + (lane >> 4) * 8;
    const int kb_off = ((lane >> 3) & 1) * 8;

    uint32_t aLane0[2], bLane0[4];
#pragma unroll
    for (int mt = 0; mt < 2; mt++)
        aLane0[mt] = smA0 + ((wm * 32 + mt * 16 + m_off) * RSTRIDE + ka_off) * 2;
#pragma unroll
    for (int np = 0; np < 4; np++)
        bLane0[np] = smB0 + ((wn * 64 + np * 16 + n_off) * RSTRIDE + kb_off) * 2;

    auto LOAD_STAGE = [&](int s) {
        const uint32_t boff = (uint32_t)(s % 3) * PAIR_BYTES;
        const int k0 = s * KS;
#pragma unroll
        for (int i = 0; i < 4; i++) {
            const bool okA = (m0 + rowc[i]) < M_G;
            const __half* gA =
                okA ? (At + (size_t)(m0 + rowc[i]) * KP + k0 + kcc[i] * 8) : At;
            const uint32_t dstA =
                smA0 + boff + (uint32_t)(rowc[i] * (RSTRIDE * 2) + kcc[i] * 16);
            const int szA = okA ? 16 : 0;
            asm volatile("cp.async.cg.shared.global [%0], [%1], 16, %2;"
                         :: "r"(dstA), "l"(gA), "r"(szA));

            const bool okB = (n0 + rowc[i]) < N_G;
            const __half* gB =
                okB ? (Xb + (size_t)(n0 + rowc[i]) * KP + k0 + kcc[i] * 8) : Xb;
            const uint32_t dstB =
                smB0 + boff + (uint32_t)(rowc[i] * (RSTRIDE * 2) + kcc[i] * 16);
            const int szB = okB ? 16 : 0;
            asm volatile("cp.async.cg.shared.global [%0], [%1], 16, %2;"
                         :: "r"(dstB), "l"(gB), "r"(szB));
        }
        asm volatile("cp.async.commit_group;" ::: "memory");
    };

    auto COMPUTE = [&](int s) {
        const uint32_t boff = (uint32_t)(s % 3) * PAIR_BYTES;
#pragma unroll
        for (int kk = 0; kk < 4; kk++) {
            const uint32_t kb = boff + kk * 32;

            uint32_t a[2][4];
#pragma unroll
            for (int mt = 0; mt < 2; mt++)
                asm volatile(
                    "ldmatrix.sync.aligned.m8n8.x4.shared.b16 {%0,%1,%2,%3}, [%4];"
                    : "=r"(a[mt][0]), "=r"(a[mt][1]), "=r"(a[mt][2]), "=r"(a[mt][3])
                    : "r"(aLane0[mt] + kb));

            uint32_t bf[8][2];
#pragma unroll
            for (int np = 0; np < 4; np++) {
                uint32_t r0, r1, r2, r3;
                asm volatile(
                    "ldmatrix.sync.aligned.m8n8.x4.shared.b16 {%0,%1,%2,%3}, [%4];"
                    : "=r"(r0), "=r"(r1), "=r"(r2), "=r"(r3)
                    : "r"(bLane0[np] + kb));
                bf[2 * np][0]     = r0;  bf[2 * np][1]     = r1;
                bf[2 * np + 1][0] = r2;  bf[2 * np + 1][1] = r3;
            }

#pragma unroll
            for (int mt = 0; mt < 2; mt++)
#pragma unroll
                for (int nt = 0; nt < 8; nt++)
                    asm volatile(
                        "mma.sync.aligned.m16n8k16.row.col.f32.f16.f16.f32 "
                        "{%0,%1,%2,%3}, {%4,%5,%6,%7}, {%8,%9}, {%0,%1,%2,%3};"
                        : "+f"(acc[mt][nt][0]), "+f"(acc[mt][nt][1]),
                          "+f"(acc[mt][nt][2]), "+f"(acc[mt][nt][3])
                        : "r"(a[mt][0]), "r"(a[mt][1]), "r"(a[mt][2]), "r"(a[mt][3]),
                          "r"(bf[nt][0]), "r"(bf[nt][1]));
        }
    };

    LOAD_STAGE(0);
    LOAD_STAGE(1);
    for (int s = 0; s < NST; s++) {
        if (s + 1 < NST)
            asm volatile("cp.async.wait_group 1;" ::: "memory");
        else
            asm volatile("cp.async.wait_group 0;" ::: "memory");
        __syncthreads();
        COMPUTE(s);
        if (s + 2 < NST) LOAD_STAGE(s + 2);
    }

    const int rbase = lane >> 2;
    const int cbase = (lane & 3) * 2;
#pragma unroll
    for (int mt = 0; mt < 2; mt++) {
#pragma unroll
        for (int nt = 0; nt < 8; nt++) {
            const int row = m0 + wm * 32 + mt * 16 + rbase;
            const int col = n0 + wn * 64 + nt * 8 + cbase;
            if (col < N_G) {
                if (row < M_G)
                    *reinterpret_cast<float2*>(Cp + (size_t)row * N_G + col) =
                        make_float2(acc[mt][nt][0], acc[mt][nt][1]);
                if (row + 8 < M_G)
                    *reinterpret_cast<float2*>(Cp + (size_t)(row + 8) * N_G + col) =
                        make_float2(acc[mt][nt][2], acc[mt][nt][3]);
            }
        }
    }
}

// ---------------------------------------------------------------------------
// Kernel 2: fused tail v5 — logits PREFETCHED via cp.async into smem at
// kernel start (latency hidden behind phases A+B); dynamic smem pool.
// Pool layout (floats): ls 7056 | xs 3168 | fs 8100 | w1s 243 | w2s 81
// = 18648 floats = 74592 bytes.
// ---------------------------------------------------------------------------
#define NT2 256
#define LS_F   (9 * 28 * 28)          // 7056
#define XS_F   (3 * 32 * 33)          // 3168
#define FS_F   8100
#define TAIL_SMEM ((LS_F + XS_F + FS_F + 243 + 81) * 4)   // 74592

__global__ __launch_bounds__(NT2, 3)
void fused_tail_kernel(const float* __restrict__ x,
                       const float* __restrict__ w1,
                       const float* __restrict__ w2,
                       float* __restrict__ out)
{
    extern __shared__ __align__(16) float pool[];
    float* ls  = pool;                                   // [9][28][28]
    float (*xs)[32][33] = reinterpret_cast<float (*)[32][33]>(pool + LS_F);
    float* fs  = pool + LS_F + XS_F;                     // [9][30][30]
    float* w1s = pool + LS_F + XS_F + FS_F;              // [9][27]
    float* w2s = w1s + 243;                              // [9][9]

    const int bc  = blockIdx.z;
    const int b   = bc / C_OUT;
    const int c   = bc % C_OUT;
    const int ty0 = blockIdx.y * 28;
    const int tx0 = blockIdx.x * 28;
    const int tid = threadIdx.x;

    // --- prefetch logits tile (9 x 28x28) via cp.async: 1764 16B chunks ---
    const float* lblk = g_logits + ((size_t)b * M_G + (size_t)c * KK) * N_G;
    for (int ch = tid; ch < 9 * 28 * 7; ch += NT2) {
        const int i  = ch / 196;
        const int r  = ch - i * 196;
        const int oy = r / 7;
        const int cx = r - oy * 7;
        const float* src = lblk + (size_t)i * N_G
                         + (ty0 + oy) * W_IMG + tx0 + cx * 4;
        const uint32_t dst = smem_u32(ls + i * 784 + oy * 28 + cx * 4);
        asm volatile("cp.async.cg.shared.global [%0], [%1], 16;"
                     :: "r"(dst), "l"(src));
    }
    asm volatile("cp.async.commit_group;" ::: "memory");

    // --- weights + x tile (regular loads; overlap with the async prefetch) ---
    for (int e = tid; e < 243; e += NT2)
        w1s[e] = w1[(size_t)(e / 27) * (C_OUT * 27) + c * 27 + (e % 27)];
    for (int e = tid; e < 81; e += NT2)
        w2s[e] = w2[(size_t)(e / 9) * (C_OUT * 9) + c * 9 + (e % 9)];

    const float* xb = x + ((size_t)b * CIN + 3 * c) * HW;
    for (int e = tid; e < 3 * 32 * 32; e += NT2) {
        const int j  = e >> 10;
        const int r  = e & 1023;
        const int ly = r >> 5;
        const int lx = r & 31;
        const int gy = ty0 - 2 + ly;
        const int gx = tx0 - 2 + lx;
        float v = 0.f;
        if ((unsigned)gy < (unsigned)H_IMG && (unsigned)gx < (unsigned)W_IMG)
            v = xb[(size_t)j * HW + gy * W_IMG + gx];
        xs[j][ly][lx] = v;
    }
    __syncthreads();

    // Phase B: conv1+ReLU, width-5 strips (conflict-free with padded xs).
    for (int t = tid; t < 9 * 30 * 6; t += NT2) {
        const int i   = t / 180;
        const int r   = t - i * 180;
        const int fy  = r / 6;
        const int fx0 = (r - fy * 6) * 5;
        const int fgy = ty0 - 1 + fy;

        float acc[5] = {0.f, 0.f, 0.f, 0.f, 0.f};
        const float* wp = &w1s[i * 27];
#pragma unroll
        for (int j = 0; j < 3; j++) {
#pragma unroll
            for (int kh = 0; kh < 3; kh++) {
                float xr[7];
#pragma unroll
                for (int q = 0; q < 7; q++)
                    xr[q] = xs[j][fy + kh][fx0 + q];
                const float w0  = wp[j * 9 + kh * 3 + 0];
                const float w1v = wp[j * 9 + kh * 3 + 1];
                const float w2v = wp[j * 9 + kh * 3 + 2];
#pragma unroll
                for (int px = 0; px < 5; px++)
                    acc[px] = fmaf(w0, xr[px],
                              fmaf(w1v, xr[px + 1],
                              fmaf(w2v, xr[px + 2], acc[px])));
            }
        }
        float* fsd = &fs[i * 900 + fy * 30 + fx0];
        const bool yok = (unsigned)fgy < (unsigned)H_IMG;
#pragma unroll
        for (int px = 0; px < 5; px++) {
            const int fgx = tx0 - 1 + fx0 + px;
            float v = 0.f;
            if (yok && (unsigned)fgx < (unsigned)W_IMG)
                v = fmaxf(acc[px], 0.f);
            fsd[px] = v;
        }
    }
    // ensure logits prefetch landed, then make all smem writes visible
    asm volatile("cp.async.wait_group 0;" ::: "memory");
    __syncthreads();

    // Phase C: width-2 pixel strips, logits from smem (ls).
    float* ob = out + ((size_t)b * C_OUT + c) * HW;
    for (int e = tid; e < 28 * 14; e += NT2) {
        const int oy  = e / 14;
        const int ox0 = (e - oy * 14) * 2;
        const int p   = (ty0 + oy) * W_IMG + (tx0 + ox0);

        float2 l2[9];
#pragma unroll
        for (int i = 0; i < 9; i++)
            l2[i] = *reinterpret_cast<const float2*>(ls + i * 784 + oy * 28 + ox0);

        float mx0 = l2[0].x, mx1 = l2[0].y;
#pragma unroll
        for (int i = 1; i < 9; i++) {
            mx0 = fmaxf(mx0, l2[i].x);
            mx1 = fmaxf(mx1, l2[i].y);
        }
        float s0 = 0.f, s1 = 0.f;
#pragma unroll
        for (int i = 0; i < 9; i++) {
            l2[i].x = __expf(l2[i].x - mx0);  s0 += l2[i].x;
            l2[i].y = __expf(l2[i].y - mx1);  s1 += l2[i].y;
        }
        const float inv0 = 1.f / s0;
        const float inv1 = 1.f / s1;

        float acc0 = 0.f, acc1 = 0.f;
#pragma unroll
        for (int i = 0; i < 9; i++) {
            const float* fpi = &fs[i * 900 + oy * 30 + ox0];
            float dw0 = 0.f, dw1 = 0.f;
#pragma unroll
            for (int kh = 0; kh < 3; kh++) {
                const float2 wlo = *reinterpret_cast<const float2*>(fpi + kh * 30);
                const float2 whi = *reinterpret_cast<const float2*>(fpi + kh * 30 + 2);
                const float wv0 = w2s[i * 9 + kh * 3 + 0];
                const float wv1 = w2s[i * 9 + kh * 3 + 1];
                const float wv2 = w2s[i * 9 + kh * 3 + 2];
                dw0 = fmaf(wv0, wlo.x, fmaf(wv1, wlo.y, fmaf(wv2, whi.x, dw0)));
                dw1 = fmaf(wv0, wlo.y, fmaf(wv1, whi.x, fmaf(wv2, whi.y, dw1)));
            }
            acc0 = fmaf(l2[i].x * inv0, dw0, acc0);
            acc1 = fmaf(l2[i].y * inv1, dw1, acc1);
        }
        *reinterpret_cast<float2*>(ob + p) = make_float2(acc0, acc1);
    }
}

// ---------------------------------------------------------------------------
extern "C" void kernel_launch(void* const* d_in, const int* in_sizes, int n_in,
                              void* d_out, int out_size)
{
    const float* x    = nullptr;
    const float* fc_w = nullptr;
    const float* w1   = nullptr;
    const float* w2   = nullptr;
    for (int i = 0; i < n_in; i++) {
        switch (in_sizes[i]) {
            case B_SZ * CIN * HW:        x    = (const float*)d_in[i]; break;
            case C_OUT * KK * CIN:       fc_w = (const float*)d_in[i]; break;
            case KK * C_OUT * 3 * 3 * 3: w1   = (const float*)d_in[i]; break;
            case KK * C_OUT * 3 * 3:     w2   = (const float*)d_in[i]; break;
            default: break;
        }
    }
    float* out = (float*)d_out;

    cudaFuncSetAttribute(gemm_mma_kernel,
                         cudaFuncAttributeMaxDynamicSharedMemorySize,
                         DSMEM_BYTES);
    cudaFuncSetAttribute(fused_tail_kernel,
                         cudaFuncAttributeMaxDynamicSharedMemorySize,
                         TAIL_SMEM);

    // Pack (plain fp16)
    pack_A_kernel<<<(M_G * K_G + 255) / 256, 256>>>(fc_w);
    dim3 gx(N_G / 32, K_G / 32, B_SZ);          // 98 x 18 x 8
    pack_X_kernel<<<gx, 256>>>(x);

    // HMMA GEMM -> g_logits
    dim3 gg((N_G + 127) / 128, (M_G + 127) / 128, B_SZ);   // 25 x 14 x 8
    gemm_mma_kernel<<<gg, 256, DSMEM_BYTES>>>();

    // fused tail v5 (logits prefetch)
    dim3 g2(2, 2, B_SZ * C_OUT);
    fused_tail_kernel<<<g2, NT2, TAIL_SMEM>>>(x, w1, w2, out);
}